// round 11
// baseline (speedup 1.0000x reference)
#include <cuda_runtime.h>
#include <cuda_bf16.h>
#include <cstdint>

// Problem constants
#define BB 2
#define NN 4096
#define MM 4096
#define DD 512
#define HH 8
#define PP 64

// ---------------- scratch for projected Q/K/V ----------------
__device__ float g_Q[(size_t)BB * NN * DD];
__device__ float g_K[(size_t)BB * MM * DD];
__device__ float g_V[(size_t)BB * MM * DD];

__device__ __forceinline__ uint32_t f2tf(float f) {
    uint32_t u;
    asm("cvt.rna.tf32.f32 %0, %1;" : "=r"(u) : "f"(f));
    return u;
}
__device__ __forceinline__ float ex2(float x) {
    float y;
    asm("ex2.approx.ftz.f32 %0, %1;" : "=f"(y) : "f"(x));
    return y;
}
__device__ __forceinline__ void mma8(float* c, const uint32_t* a, uint32_t b0, uint32_t b1) {
    asm volatile(
        "mma.sync.aligned.m16n8k8.row.col.f32.tf32.tf32.f32 "
        "{%0,%1,%2,%3},{%4,%5,%6,%7},{%8,%9},{%0,%1,%2,%3};"
        : "+f"(c[0]), "+f"(c[1]), "+f"(c[2]), "+f"(c[3])
        : "r"(a[0]), "r"(a[1]), "r"(a[2]), "r"(a[3]), "r"(b0), "r"(b1));
}

// ---------------- tf32 mma projection GEMM ----------------
// Y[8192,512] = X[8192,512] @ W[512,512] + b
// CTA tile 128x64, K-chunk 32. 8 warps: 4 along M (32 rows each), 2 along N (32 cols each).
#define PBM 128
#define PBN 64
#define PBK 32
#define XSTR 36
#define WSTR 36

__global__ __launch_bounds__(256) void gemm_tf32_kernel(
    const float* __restrict__ X, const float* __restrict__ W,
    const float* __restrict__ bias, float* __restrict__ Y)
{
    __shared__ float Xs[PBM * XSTR];
    __shared__ float Wts[PBN * WSTR];   // transposed W tile: [n][k]

    const int tid  = threadIdx.x;
    const int lane = tid & 31;
    const int warp = tid >> 5;
    const int bm = blockIdx.y * PBM;
    const int bn = blockIdx.x * PBN;
    const int rg = lane >> 2;
    const int rt = lane & 3;
    const int wm = (warp & 3) * 32;
    const int wn = (warp >> 2) * 32;

    float acc[2][4][4];
#pragma unroll
    for (int mt = 0; mt < 2; mt++)
#pragma unroll
        for (int nt = 0; nt < 4; nt++)
#pragma unroll
            for (int i = 0; i < 4; i++) acc[mt][nt][i] = 0.f;

    for (int k0 = 0; k0 < DD; k0 += PBK) {
        // fill Xs [128][32] (tf32-rounded): thread t -> row t>>1, col-half (t&1)*16
        {
            int r  = tid >> 1;
            int cs = (tid & 1) * 16;
            const float* src = X + (size_t)(bm + r) * DD + k0 + cs;
            float* dst = Xs + r * XSTR + cs;
#pragma unroll
            for (int j = 0; j < 4; j++) {
                float4 v = *(const float4*)(src + j * 4);
                float4 o;
                o.x = __uint_as_float(f2tf(v.x));
                o.y = __uint_as_float(f2tf(v.y));
                o.z = __uint_as_float(f2tf(v.z));
                o.w = __uint_as_float(f2tf(v.w));
                *(float4*)(dst + j * 4) = o;
            }
        }
        // fill Wts [64][32] transposed: thread t -> k = t>>3, n8 = (t&7)*8
        {
            int k  = tid >> 3;
            int n8 = (tid & 7) * 8;
            const float* src = W + (size_t)(k0 + k) * DD + bn + n8;
#pragma unroll
            for (int j = 0; j < 8; j++)
                Wts[(n8 + j) * WSTR + k] = __uint_as_float(f2tf(src[j]));
        }
        __syncthreads();

#pragma unroll
        for (int kk = 0; kk < 4; kk++) {
            uint32_t A[2][4];
#pragma unroll
            for (int mt = 0; mt < 2; mt++) {
                const float* ab = Xs + (wm + mt * 16 + rg) * XSTR + kk * 8 + rt;
                A[mt][0] = __float_as_uint(ab[0]);
                A[mt][1] = __float_as_uint(ab[8 * XSTR]);
                A[mt][2] = __float_as_uint(ab[4]);
                A[mt][3] = __float_as_uint(ab[8 * XSTR + 4]);
            }
#pragma unroll
            for (int nt = 0; nt < 4; nt++) {
                const float* bb = Wts + (wn + nt * 8 + rg) * WSTR + kk * 8 + rt;
                uint32_t b0 = __float_as_uint(bb[0]);
                uint32_t b1 = __float_as_uint(bb[4]);
                mma8(acc[0][nt], A[0], b0, b1);
                mma8(acc[1][nt], A[1], b0, b1);
            }
        }
        __syncthreads();
    }

    // epilogue: + bias, store
#pragma unroll
    for (int mt = 0; mt < 2; mt++) {
#pragma unroll
        for (int half = 0; half < 2; half++) {
            const int row = bm + wm + mt * 16 + half * 8 + rg;
#pragma unroll
            for (int nt = 0; nt < 4; nt++) {
                const int col = bn + wn + nt * 8 + rt * 2;
                float2 o;
                o.x = acc[mt][nt][half * 2]     + bias[col];
                o.y = acc[mt][nt][half * 2 + 1] + bias[col + 1];
                *(float2*)(Y + (size_t)row * DD + col) = o;
            }
        }
    }
}

// ---------------- tf32 mma flash attention ----------------
// Block: 128 q-rows, 4 warps, each warp 32 rows (2 m16 tiles). KV tile 64.
#define FTQ 128
#define FTK 64
#define QSTR 68
#define KSTR 68
#define VSTR 72

#define FLASH_SMEM_FLOATS (FTQ * QSTR + FTK * KSTR + FTK * VSTR)
#define FLASH_SMEM_BYTES  (FLASH_SMEM_FLOATS * 4)

__global__ __launch_bounds__(128, 3) void flash_mma_kernel(float* __restrict__ out)
{
    extern __shared__ float sm[];
    float* Qs = sm;                    // [FTQ][QSTR]
    float* Ks = Qs + FTQ * QSTR;       // [FTK][KSTR]
    float* Vs = Ks + FTK * KSTR;       // [FTK][VSTR]

    const int tid  = threadIdx.x;
    const int lane = tid & 31;
    const int warp = tid >> 5;
    const int n0 = blockIdx.x * FTQ;
    const int h  = blockIdx.y;
    const int b  = blockIdx.z;

    const float* Qg = g_Q + ((size_t)b * NN + n0) * DD + h * PP;
    const float* Kg = g_K + (size_t)b * MM * DD + h * PP;
    const float* Vg = g_V + (size_t)b * MM * DD + h * PP;

    // fold 1/sqrt(P) and log2(e) into Q so softmax is pure ex2
    const float qscale = 0.125f * 1.4426950408889634f;

    // Q fill: one row per thread, 16 float4, scale + tf32-round
    {
        const float* src = Qg + (size_t)tid * DD;
        float* dst = Qs + tid * QSTR;
#pragma unroll
        for (int c = 0; c < 16; c++) {
            float4 v = *(const float4*)(src + c * 4);
            float4 o;
            o.x = __uint_as_float(f2tf(v.x * qscale));
            o.y = __uint_as_float(f2tf(v.y * qscale));
            o.z = __uint_as_float(f2tf(v.z * qscale));
            o.w = __uint_as_float(f2tf(v.w * qscale));
            *(float4*)(dst + c * 4) = o;
        }
    }

    const int rg = lane >> 2;
    const int rt = lane & 3;
    const int wm = warp * 32;

    float O[2][8][4];
#pragma unroll
    for (int mt = 0; mt < 2; mt++)
#pragma unroll
        for (int nt = 0; nt < 8; nt++)
#pragma unroll
            for (int i = 0; i < 4; i++) O[mt][nt][i] = 0.f;

    float mrow[4] = {-1e30f, -1e30f, -1e30f, -1e30f};
    float lrow[4] = {0.f, 0.f, 0.f, 0.f};

    const int psrc  = (lane & ~3) | (rt >> 1);
    const int psrc2 = psrc + 2;
    const bool odd  = (lane & 1);

    __syncthreads();

    for (int kt = 0; kt < MM; kt += FTK) {
        {
            int r = tid >> 1;
            int cs = (tid & 1) * 32;
            const float* ksrc = Kg + (size_t)(kt + r) * DD + cs;
            const float* vsrc = Vg + (size_t)(kt + r) * DD + cs;
            float* kdst = Ks + r * KSTR + cs;
            float* vdst = Vs + r * VSTR + cs;
#pragma unroll
            for (int c = 0; c < 8; c++) {
                float4 k4 = *(const float4*)(ksrc + c * 4);
                float4 v4 = *(const float4*)(vsrc + c * 4);
                float4 ko, vo;
                ko.x = __uint_as_float(f2tf(k4.x));
                ko.y = __uint_as_float(f2tf(k4.y));
                ko.z = __uint_as_float(f2tf(k4.z));
                ko.w = __uint_as_float(f2tf(k4.w));
                vo.x = __uint_as_float(f2tf(v4.x));
                vo.y = __uint_as_float(f2tf(v4.y));
                vo.z = __uint_as_float(f2tf(v4.z));
                vo.w = __uint_as_float(f2tf(v4.w));
                *(float4*)(kdst + c * 4) = ko;
                *(float4*)(vdst + c * 4) = vo;
            }
        }
        __syncthreads();

        // ---- S = Q K^T (exp2 domain) ----
        float S[2][8][4];
#pragma unroll
        for (int mt = 0; mt < 2; mt++)
#pragma unroll
            for (int nt = 0; nt < 8; nt++)
#pragma unroll
                for (int i = 0; i < 4; i++) S[mt][nt][i] = 0.f;

#pragma unroll
        for (int kk = 0; kk < 8; kk++) {
            uint32_t A[2][4];
#pragma unroll
            for (int mt = 0; mt < 2; mt++) {
                const float* qb = Qs + (wm + mt * 16 + rg) * QSTR + kk * 8 + rt;
                A[mt][0] = __float_as_uint(qb[0]);
                A[mt][1] = __float_as_uint(qb[8 * QSTR]);
                A[mt][2] = __float_as_uint(qb[4]);
                A[mt][3] = __float_as_uint(qb[8 * QSTR + 4]);
            }
#pragma unroll
            for (int nt = 0; nt < 8; nt++) {
                const float* kb = Ks + (nt * 8 + rg) * KSTR + kk * 8 + rt;
                uint32_t b0 = __float_as_uint(kb[0]);
                uint32_t b1 = __float_as_uint(kb[4]);
                mma8(S[0][nt], A[0], b0, b1);
                mma8(S[1][nt], A[1], b0, b1);
            }
        }

        // ---- online softmax (base-2) ----
#pragma unroll
        for (int mt = 0; mt < 2; mt++) {
#pragma unroll
            for (int half = 0; half < 2; half++) {
                const int gi = mt * 2 + half;
                float mx = -1e30f;
#pragma unroll
                for (int nt = 0; nt < 8; nt++)
                    mx = fmaxf(mx, fmaxf(S[mt][nt][half * 2], S[mt][nt][half * 2 + 1]));
                mx = fmaxf(mx, __shfl_xor_sync(0xffffffffu, mx, 1));
                mx = fmaxf(mx, __shfl_xor_sync(0xffffffffu, mx, 2));
                const float mnew = fmaxf(mrow[gi], mx);
                const float corr = ex2(mrow[gi] - mnew);
                mrow[gi] = mnew;
                lrow[gi] *= corr;
                float lsum = 0.f;
#pragma unroll
                for (int nt = 0; nt < 8; nt++) {
                    O[mt][nt][half * 2]     *= corr;
                    O[mt][nt][half * 2 + 1] *= corr;
                    float p0 = ex2(S[mt][nt][half * 2]     - mnew);
                    float p1 = ex2(S[mt][nt][half * 2 + 1] - mnew);
                    lsum += p0 + p1;
                    S[mt][nt][half * 2]     = __uint_as_float(f2tf(p0));
                    S[mt][nt][half * 2 + 1] = __uint_as_float(f2tf(p1));
                }
                lrow[gi] += lsum;
            }
        }

        // ---- O += P V ----
#pragma unroll
        for (int kk2 = 0; kk2 < 8; kk2++) {
            uint32_t A[2][4];
#pragma unroll
            for (int mt = 0; mt < 2; mt++) {
                uint32_t p0 = __float_as_uint(S[mt][kk2][0]);
                uint32_t p1 = __float_as_uint(S[mt][kk2][1]);
                uint32_t p2 = __float_as_uint(S[mt][kk2][2]);
                uint32_t p3 = __float_as_uint(S[mt][kk2][3]);
                uint32_t u0 = __shfl_sync(0xffffffffu, p0, psrc);
                uint32_t u1 = __shfl_sync(0xffffffffu, p1, psrc);
                A[mt][0] = odd ? u1 : u0;
                uint32_t u2 = __shfl_sync(0xffffffffu, p2, psrc);
                uint32_t u3 = __shfl_sync(0xffffffffu, p3, psrc);
                A[mt][1] = odd ? u3 : u2;
                uint32_t v0 = __shfl_sync(0xffffffffu, p0, psrc2);
                uint32_t v1 = __shfl_sync(0xffffffffu, p1, psrc2);
                A[mt][2] = odd ? v1 : v0;
                uint32_t v2 = __shfl_sync(0xffffffffu, p2, psrc2);
                uint32_t v3 = __shfl_sync(0xffffffffu, p3, psrc2);
                A[mt][3] = odd ? v3 : v2;
            }
#pragma unroll
            for (int nt = 0; nt < 8; nt++) {
                const float* vb = Vs + (kk2 * 8 + rt) * VSTR + nt * 8 + rg;
                uint32_t b0 = __float_as_uint(vb[0]);
                uint32_t b1 = __float_as_uint(vb[4 * VSTR]);
                mma8(O[0][nt], A[0], b0, b1);
                mma8(O[1][nt], A[1], b0, b1);
            }
        }
        __syncthreads();
    }

    // ---- epilogue ----
#pragma unroll
    for (int gi = 0; gi < 4; gi++) {
        float l = lrow[gi];
        l += __shfl_xor_sync(0xffffffffu, l, 1);
        l += __shfl_xor_sync(0xffffffffu, l, 2);
        lrow[gi] = 1.f / l;
    }
#pragma unroll
    for (int mt = 0; mt < 2; mt++) {
#pragma unroll
        for (int half = 0; half < 2; half++) {
            const int row = n0 + wm + mt * 16 + half * 8 + rg;
            const float inv = lrow[mt * 2 + half];
            float* ob = out + ((size_t)b * NN + row) * DD + h * PP;
#pragma unroll
            for (int nt = 0; nt < 8; nt++) {
                float2 o;
                o.x = O[mt][nt][half * 2]     * inv;
                o.y = O[mt][nt][half * 2 + 1] * inv;
                *(float2*)(ob + nt * 8 + 2 * rt) = o;
            }
        }
    }
}

// ---------------- launch ----------------
extern "C" void kernel_launch(void* const* d_in, const int* in_sizes, int n_in,
                              void* d_out, int out_size)
{
    const float* queries = (const float*)d_in[0];
    const float* keys    = (const float*)d_in[1];
    const float* values  = (const float*)d_in[2];
    const float* Wq      = (const float*)d_in[3];
    const float* bq      = (const float*)d_in[4];
    const float* Wk      = (const float*)d_in[5];
    const float* bk      = (const float*)d_in[6];
    const float* Wv      = (const float*)d_in[7];
    const float* bv      = (const float*)d_in[8];
    float* out = (float*)d_out;

    float *pQ, *pK, *pV;
    cudaGetSymbolAddress((void**)&pQ, g_Q);
    cudaGetSymbolAddress((void**)&pK, g_K);
    cudaGetSymbolAddress((void**)&pV, g_V);

    // projections: [8192, 512] @ [512, 512] + b  (tf32 mma)
    dim3 pgrid(DD / PBN, (BB * NN) / PBM);
    gemm_tf32_kernel<<<pgrid, 256>>>(queries, Wq, bq, pQ);
    gemm_tf32_kernel<<<pgrid, 256>>>(keys,    Wk, bk, pK);
    gemm_tf32_kernel<<<pgrid, 256>>>(values,  Wv, bv, pV);

    cudaFuncSetAttribute(flash_mma_kernel, cudaFuncAttributeMaxDynamicSharedMemorySize,
                         FLASH_SMEM_BYTES);
    dim3 fgrid(NN / FTQ, HH, BB);
    flash_mma_kernel<<<fgrid, 128, FLASH_SMEM_BYTES>>>(out);
}

// round 13
// speedup vs baseline: 1.2180x; 1.2180x over previous
#include <cuda_runtime.h>
#include <cuda_bf16.h>
#include <cstdint>

// Problem constants
#define BB 2
#define NN 4096
#define MM 4096
#define DD 512
#define HH 8
#define PP 64

// ---------------- scratch for projected Q/K/V ----------------
__device__ float g_Q[(size_t)BB * NN * DD];
__device__ float g_K[(size_t)BB * MM * DD];
__device__ float g_V[(size_t)BB * MM * DD];

__device__ __forceinline__ uint32_t f2tf(float f) {
    uint32_t u;
    asm("cvt.rna.tf32.f32 %0, %1;" : "=r"(u) : "f"(f));
    return u;
}
__device__ __forceinline__ float ex2(float x) {
    float y;
    asm("ex2.approx.ftz.f32 %0, %1;" : "=f"(y) : "f"(x));
    return y;
}
__device__ __forceinline__ void mma8(float* c, const uint32_t* a, uint32_t b0, uint32_t b1) {
    asm volatile(
        "mma.sync.aligned.m16n8k8.row.col.f32.tf32.tf32.f32 "
        "{%0,%1,%2,%3},{%4,%5,%6,%7},{%8,%9},{%0,%1,%2,%3};"
        : "+f"(c[0]), "+f"(c[1]), "+f"(c[2]), "+f"(c[3])
        : "r"(a[0]), "r"(a[1]), "r"(a[2]), "r"(a[3]), "r"(b0), "r"(b1));
}

// ---------------- tf32 mma projection GEMM (unchanged: measured win) ----------------
// Y[8192,512] = X[8192,512] @ W[512,512] + b
#define PBM 128
#define PBN 64
#define PBK 32
#define XSTR 36
#define WSTR 36

__global__ __launch_bounds__(256) void gemm_tf32_kernel(
    const float* __restrict__ X, const float* __restrict__ W,
    const float* __restrict__ bias, float* __restrict__ Y)
{
    __shared__ float Xs[PBM * XSTR];
    __shared__ float Wts[PBN * WSTR];   // transposed W tile: [n][k]

    const int tid  = threadIdx.x;
    const int lane = tid & 31;
    const int warp = tid >> 5;
    const int bm = blockIdx.y * PBM;
    const int bn = blockIdx.x * PBN;
    const int rg = lane >> 2;
    const int rt = lane & 3;
    const int wm = (warp & 3) * 32;
    const int wn = (warp >> 2) * 32;

    float acc[2][4][4];
#pragma unroll
    for (int mt = 0; mt < 2; mt++)
#pragma unroll
        for (int nt = 0; nt < 4; nt++)
#pragma unroll
            for (int i = 0; i < 4; i++) acc[mt][nt][i] = 0.f;

    for (int k0 = 0; k0 < DD; k0 += PBK) {
        {
            int r  = tid >> 1;
            int cs = (tid & 1) * 16;
            const float* src = X + (size_t)(bm + r) * DD + k0 + cs;
            float* dst = Xs + r * XSTR + cs;
#pragma unroll
            for (int j = 0; j < 4; j++) {
                float4 v = *(const float4*)(src + j * 4);
                float4 o;
                o.x = __uint_as_float(f2tf(v.x));
                o.y = __uint_as_float(f2tf(v.y));
                o.z = __uint_as_float(f2tf(v.z));
                o.w = __uint_as_float(f2tf(v.w));
                *(float4*)(dst + j * 4) = o;
            }
        }
        {
            int k  = tid >> 3;
            int n8 = (tid & 7) * 8;
            const float* src = W + (size_t)(k0 + k) * DD + bn + n8;
#pragma unroll
            for (int j = 0; j < 8; j++)
                Wts[(n8 + j) * WSTR + k] = __uint_as_float(f2tf(src[j]));
        }
        __syncthreads();

#pragma unroll
        for (int kk = 0; kk < 4; kk++) {
            uint32_t A[2][4];
#pragma unroll
            for (int mt = 0; mt < 2; mt++) {
                const float* ab = Xs + (wm + mt * 16 + rg) * XSTR + kk * 8 + rt;
                A[mt][0] = __float_as_uint(ab[0]);
                A[mt][1] = __float_as_uint(ab[8 * XSTR]);
                A[mt][2] = __float_as_uint(ab[4]);
                A[mt][3] = __float_as_uint(ab[8 * XSTR + 4]);
            }
#pragma unroll
            for (int nt = 0; nt < 4; nt++) {
                const float* bb = Wts + (wn + nt * 8 + rg) * WSTR + kk * 8 + rt;
                uint32_t b0 = __float_as_uint(bb[0]);
                uint32_t b1 = __float_as_uint(bb[4]);
                mma8(acc[0][nt], A[0], b0, b1);
                mma8(acc[1][nt], A[1], b0, b1);
            }
        }
        __syncthreads();
    }

#pragma unroll
    for (int mt = 0; mt < 2; mt++) {
#pragma unroll
        for (int half = 0; half < 2; half++) {
            const int row = bm + wm + mt * 16 + half * 8 + rg;
#pragma unroll
            for (int nt = 0; nt < 4; nt++) {
                const int col = bn + wn + nt * 8 + rt * 2;
                float2 o;
                o.x = acc[mt][nt][half * 2]     + bias[col];
                o.y = acc[mt][nt][half * 2 + 1] + bias[col + 1];
                *(float2*)(Y + (size_t)row * DD + col) = o;
            }
        }
    }
}

// ---------------- tf32 mma flash attention ----------------
// Block: 128 q-rows, 4 warps, each warp 32 rows (2 m16 tiles). KV tile 64.
// Q fragments hoisted to registers (loop-invariant); minBlocks reverted to 2.
#define FTQ 128
#define FTK 64
#define QSTR 68
#define KSTR 68
#define VSTR 72

#define FLASH_SMEM_FLOATS (FTQ * QSTR + FTK * KSTR + FTK * VSTR)
#define FLASH_SMEM_BYTES  (FLASH_SMEM_FLOATS * 4)

__global__ __launch_bounds__(128, 2) void flash_mma_kernel(float* __restrict__ out)
{
    extern __shared__ float sm[];
    float* Qs = sm;                    // [FTQ][QSTR] (staging only)
    float* Ks = Qs + FTQ * QSTR;       // [FTK][KSTR]
    float* Vs = Ks + FTK * KSTR;       // [FTK][VSTR]

    const int tid  = threadIdx.x;
    const int lane = tid & 31;
    const int warp = tid >> 5;
    const int n0 = blockIdx.x * FTQ;
    const int h  = blockIdx.y;
    const int b  = blockIdx.z;

    const float* Qg = g_Q + ((size_t)b * NN + n0) * DD + h * PP;
    const float* Kg = g_K + (size_t)b * MM * DD + h * PP;
    const float* Vg = g_V + (size_t)b * MM * DD + h * PP;

    // fold 1/sqrt(P) and log2(e) into Q so softmax is pure ex2
    const float qscale = 0.125f * 1.4426950408889634f;

    // Q staging: one row per thread, coalesced, scale + tf32-round
    {
        const float* src = Qg + (size_t)tid * DD;
        float* dst = Qs + tid * QSTR;
#pragma unroll
        for (int c = 0; c < 16; c++) {
            float4 v = *(const float4*)(src + c * 4);
            float4 o;
            o.x = __uint_as_float(f2tf(v.x * qscale));
            o.y = __uint_as_float(f2tf(v.y * qscale));
            o.z = __uint_as_float(f2tf(v.z * qscale));
            o.w = __uint_as_float(f2tf(v.w * qscale));
            *(float4*)(dst + c * 4) = o;
        }
    }

    const int rg = lane >> 2;
    const int rt = lane & 3;
    const int wm = warp * 32;

    __syncthreads();

    // ---- hoist Q A-fragments into registers (loop-invariant across KV tiles) ----
    uint32_t QA[2][8][4];
#pragma unroll
    for (int mt = 0; mt < 2; mt++) {
#pragma unroll
        for (int kk = 0; kk < 8; kk++) {
            const float* qb = Qs + (wm + mt * 16 + rg) * QSTR + kk * 8 + rt;
            QA[mt][kk][0] = __float_as_uint(qb[0]);
            QA[mt][kk][1] = __float_as_uint(qb[8 * QSTR]);
            QA[mt][kk][2] = __float_as_uint(qb[4]);
            QA[mt][kk][3] = __float_as_uint(qb[8 * QSTR + 4]);
        }
    }

    float O[2][8][4];
#pragma unroll
    for (int mt = 0; mt < 2; mt++)
#pragma unroll
        for (int nt = 0; nt < 8; nt++)
#pragma unroll
            for (int i = 0; i < 4; i++) O[mt][nt][i] = 0.f;

    float mrow[4] = {-1e30f, -1e30f, -1e30f, -1e30f};
    float lrow[4] = {0.f, 0.f, 0.f, 0.f};

    const int psrc  = (lane & ~3) | (rt >> 1);
    const int psrc2 = psrc + 2;
    const bool odd  = (lane & 1);

    for (int kt = 0; kt < MM; kt += FTK) {
        {
            int r = tid >> 1;
            int cs = (tid & 1) * 32;
            const float* ksrc = Kg + (size_t)(kt + r) * DD + cs;
            const float* vsrc = Vg + (size_t)(kt + r) * DD + cs;
            float* kdst = Ks + r * KSTR + cs;
            float* vdst = Vs + r * VSTR + cs;
#pragma unroll
            for (int c = 0; c < 8; c++) {
                float4 k4 = *(const float4*)(ksrc + c * 4);
                float4 v4 = *(const float4*)(vsrc + c * 4);
                float4 ko, vo;
                ko.x = __uint_as_float(f2tf(k4.x));
                ko.y = __uint_as_float(f2tf(k4.y));
                ko.z = __uint_as_float(f2tf(k4.z));
                ko.w = __uint_as_float(f2tf(k4.w));
                vo.x = __uint_as_float(f2tf(v4.x));
                vo.y = __uint_as_float(f2tf(v4.y));
                vo.z = __uint_as_float(f2tf(v4.z));
                vo.w = __uint_as_float(f2tf(v4.w));
                *(float4*)(kdst + c * 4) = ko;
                *(float4*)(vdst + c * 4) = vo;
            }
        }
        __syncthreads();

        // ---- S = Q K^T (exp2 domain); A-frags already in registers ----
        float S[2][8][4];
#pragma unroll
        for (int mt = 0; mt < 2; mt++)
#pragma unroll
            for (int nt = 0; nt < 8; nt++)
#pragma unroll
                for (int i = 0; i < 4; i++) S[mt][nt][i] = 0.f;

#pragma unroll
        for (int kk = 0; kk < 8; kk++) {
#pragma unroll
            for (int nt = 0; nt < 8; nt++) {
                const float* kb = Ks + (nt * 8 + rg) * KSTR + kk * 8 + rt;
                uint32_t b0 = __float_as_uint(kb[0]);
                uint32_t b1 = __float_as_uint(kb[4]);
                mma8(S[0][nt], QA[0][kk], b0, b1);
                mma8(S[1][nt], QA[1][kk], b0, b1);
            }
        }

        // ---- online softmax (base-2) ----
#pragma unroll
        for (int mt = 0; mt < 2; mt++) {
#pragma unroll
            for (int half = 0; half < 2; half++) {
                const int gi = mt * 2 + half;
                float mx = -1e30f;
#pragma unroll
                for (int nt = 0; nt < 8; nt++)
                    mx = fmaxf(mx, fmaxf(S[mt][nt][half * 2], S[mt][nt][half * 2 + 1]));
                mx = fmaxf(mx, __shfl_xor_sync(0xffffffffu, mx, 1));
                mx = fmaxf(mx, __shfl_xor_sync(0xffffffffu, mx, 2));
                const float mnew = fmaxf(mrow[gi], mx);
                const float corr = ex2(mrow[gi] - mnew);
                mrow[gi] = mnew;
                lrow[gi] *= corr;
                float lsum = 0.f;
#pragma unroll
                for (int nt = 0; nt < 8; nt++) {
                    O[mt][nt][half * 2]     *= corr;
                    O[mt][nt][half * 2 + 1] *= corr;
                    float p0 = ex2(S[mt][nt][half * 2]     - mnew);
                    float p1 = ex2(S[mt][nt][half * 2 + 1] - mnew);
                    lsum += p0 + p1;
                    S[mt][nt][half * 2]     = __uint_as_float(f2tf(p0));
                    S[mt][nt][half * 2 + 1] = __uint_as_float(f2tf(p1));
                }
                lrow[gi] += lsum;
            }
        }

        // ---- O += P V ----
#pragma unroll
        for (int kk2 = 0; kk2 < 8; kk2++) {
            uint32_t A[2][4];
#pragma unroll
            for (int mt = 0; mt < 2; mt++) {
                uint32_t p0 = __float_as_uint(S[mt][kk2][0]);
                uint32_t p1 = __float_as_uint(S[mt][kk2][1]);
                uint32_t p2 = __float_as_uint(S[mt][kk2][2]);
                uint32_t p3 = __float_as_uint(S[mt][kk2][3]);
                uint32_t u0 = __shfl_sync(0xffffffffu, p0, psrc);
                uint32_t u1 = __shfl_sync(0xffffffffu, p1, psrc);
                A[mt][0] = odd ? u1 : u0;
                uint32_t u2 = __shfl_sync(0xffffffffu, p2, psrc);
                uint32_t u3 = __shfl_sync(0xffffffffu, p3, psrc);
                A[mt][1] = odd ? u3 : u2;
                uint32_t v0 = __shfl_sync(0xffffffffu, p0, psrc2);
                uint32_t v1 = __shfl_sync(0xffffffffu, p1, psrc2);
                A[mt][2] = odd ? v1 : v0;
                uint32_t v2 = __shfl_sync(0xffffffffu, p2, psrc2);
                uint32_t v3 = __shfl_sync(0xffffffffu, p3, psrc2);
                A[mt][3] = odd ? v3 : v2;
            }
#pragma unroll
            for (int nt = 0; nt < 8; nt++) {
                const float* vb = Vs + (kk2 * 8 + rt) * VSTR + nt * 8 + rg;
                uint32_t b0 = __float_as_uint(vb[0]);
                uint32_t b1 = __float_as_uint(vb[4 * VSTR]);
                mma8(O[0][nt], A[0], b0, b1);
                mma8(O[1][nt], A[1], b0, b1);
            }
        }
        __syncthreads();
    }

    // ---- epilogue ----
#pragma unroll
    for (int gi = 0; gi < 4; gi++) {
        float l = lrow[gi];
        l += __shfl_xor_sync(0xffffffffu, l, 1);
        l += __shfl_xor_sync(0xffffffffu, l, 2);
        lrow[gi] = 1.f / l;
    }
#pragma unroll
    for (int mt = 0; mt < 2; mt++) {
#pragma unroll
        for (int half = 0; half < 2; half++) {
            const int row = n0 + wm + mt * 16 + half * 8 + rg;
            const float inv = lrow[mt * 2 + half];
            float* ob = out + ((size_t)b * NN + row) * DD + h * PP;
#pragma unroll
            for (int nt = 0; nt < 8; nt++) {
                float2 o;
                o.x = O[mt][nt][half * 2]     * inv;
                o.y = O[mt][nt][half * 2 + 1] * inv;
                *(float2*)(ob + nt * 8 + 2 * rt) = o;
            }
        }
    }
}

// ---------------- launch ----------------
extern "C" void kernel_launch(void* const* d_in, const int* in_sizes, int n_in,
                              void* d_out, int out_size)
{
    const float* queries = (const float*)d_in[0];
    const float* keys    = (const float*)d_in[1];
    const float* values  = (const float*)d_in[2];
    const float* Wq      = (const float*)d_in[3];
    const float* bq      = (const float*)d_in[4];
    const float* Wk      = (const float*)d_in[5];
    const float* bk      = (const float*)d_in[6];
    const float* Wv      = (const float*)d_in[7];
    const float* bv      = (const float*)d_in[8];
    float* out = (float*)d_out;

    float *pQ, *pK, *pV;
    cudaGetSymbolAddress((void**)&pQ, g_Q);
    cudaGetSymbolAddress((void**)&pK, g_K);
    cudaGetSymbolAddress((void**)&pV, g_V);

    // projections: [8192, 512] @ [512, 512] + b  (tf32 mma)
    dim3 pgrid(DD / PBN, (BB * NN) / PBM);
    gemm_tf32_kernel<<<pgrid, 256>>>(queries, Wq, bq, pQ);
    gemm_tf32_kernel<<<pgrid, 256>>>(keys,    Wk, bk, pK);
    gemm_tf32_kernel<<<pgrid, 256>>>(values,  Wv, bv, pV);

    cudaFuncSetAttribute(flash_mma_kernel, cudaFuncAttributeMaxDynamicSharedMemorySize,
                         FLASH_SMEM_BYTES);
    dim3 fgrid(NN / FTQ, HH, BB);
    flash_mma_kernel<<<fgrid, 128, FLASH_SMEM_BYTES>>>(out);
}

// round 16
// speedup vs baseline: 1.3335x; 1.0948x over previous
#include <cuda_runtime.h>
#include <cuda_bf16.h>
#include <cstdint>

// Problem constants
#define BB 2
#define NN 4096
#define MM 4096
#define DD 512
#define HH 8
#define PP 64

// ---------------- scratch for projected Q/K/V ----------------
__device__ float g_Q[(size_t)BB * NN * DD];
__device__ float g_K[(size_t)BB * MM * DD];
__device__ float g_V[(size_t)BB * MM * DD];

__device__ __forceinline__ uint32_t f2tf(float f) {
    uint32_t u;
    asm("cvt.rna.tf32.f32 %0, %1;" : "=r"(u) : "f"(f));
    return u;
}
__device__ __forceinline__ float ex2(float x) {
    float y;
    asm("ex2.approx.ftz.f32 %0, %1;" : "=f"(y) : "f"(x));
    return y;
}
__device__ __forceinline__ void mma8(float* c, const uint32_t* a, uint32_t b0, uint32_t b1) {
    asm volatile(
        "mma.sync.aligned.m16n8k8.row.col.f32.tf32.tf32.f32 "
        "{%0,%1,%2,%3},{%4,%5,%6,%7},{%8,%9},{%0,%1,%2,%3};"
        : "+f"(c[0]), "+f"(c[1]), "+f"(c[2]), "+f"(c[3])
        : "r"(a[0]), "r"(a[1]), "r"(a[2]), "r"(a[3]), "r"(b0), "r"(b1));
}
__device__ __forceinline__ uint32_t s2u(const void* p) {
    return (uint32_t)__cvta_generic_to_shared(p);
}
__device__ __forceinline__ void cp_async16(uint32_t dst, const void* src) {
    asm volatile("cp.async.cg.shared.global [%0], [%1], 16;" :: "r"(dst), "l"(src) : "memory");
}
__device__ __forceinline__ void cp_commit() {
    asm volatile("cp.async.commit_group;" ::: "memory");
}
__device__ __forceinline__ void cp_wait0() {
    asm volatile("cp.async.wait_group 0;" ::: "memory");
}

// ---------------- tf32 mma projection GEMM ----------------
// Y[8192,512] = X[8192,512] @ W[512,512] + b
// round_out=1: round outputs to tf32 (for K/V — lets flash consume them raw).
#define PBM 128
#define PBN 64
#define PBK 32
#define XSTR 36
#define WSTR 36

__global__ __launch_bounds__(256) void gemm_tf32_kernel(
    const float* __restrict__ X, const float* __restrict__ W,
    const float* __restrict__ bias, float* __restrict__ Y, int round_out)
{
    __shared__ float Xs[PBM * XSTR];
    __shared__ float Wts[PBN * WSTR];   // transposed W tile: [n][k]

    const int tid  = threadIdx.x;
    const int lane = tid & 31;
    const int warp = tid >> 5;
    const int bm = blockIdx.y * PBM;
    const int bn = blockIdx.x * PBN;
    const int rg = lane >> 2;
    const int rt = lane & 3;
    const int wm = (warp & 3) * 32;
    const int wn = (warp >> 2) * 32;

    float acc[2][4][4];
#pragma unroll
    for (int mt = 0; mt < 2; mt++)
#pragma unroll
        for (int nt = 0; nt < 4; nt++)
#pragma unroll
            for (int i = 0; i < 4; i++) acc[mt][nt][i] = 0.f;

    for (int k0 = 0; k0 < DD; k0 += PBK) {
        {
            int r  = tid >> 1;
            int cs = (tid & 1) * 16;
            const float* src = X + (size_t)(bm + r) * DD + k0 + cs;
            float* dst = Xs + r * XSTR + cs;
#pragma unroll
            for (int j = 0; j < 4; j++) {
                float4 v = *(const float4*)(src + j * 4);
                float4 o;
                o.x = __uint_as_float(f2tf(v.x));
                o.y = __uint_as_float(f2tf(v.y));
                o.z = __uint_as_float(f2tf(v.z));
                o.w = __uint_as_float(f2tf(v.w));
                *(float4*)(dst + j * 4) = o;
            }
        }
        {
            int k  = tid >> 3;
            int n8 = (tid & 7) * 8;
            const float* src = W + (size_t)(k0 + k) * DD + bn + n8;
#pragma unroll
            for (int j = 0; j < 8; j++)
                Wts[(n8 + j) * WSTR + k] = __uint_as_float(f2tf(src[j]));
        }
        __syncthreads();

#pragma unroll
        for (int kk = 0; kk < 4; kk++) {
            uint32_t A[2][4];
#pragma unroll
            for (int mt = 0; mt < 2; mt++) {
                const float* ab = Xs + (wm + mt * 16 + rg) * XSTR + kk * 8 + rt;
                A[mt][0] = __float_as_uint(ab[0]);
                A[mt][1] = __float_as_uint(ab[8 * XSTR]);
                A[mt][2] = __float_as_uint(ab[4]);
                A[mt][3] = __float_as_uint(ab[8 * XSTR + 4]);
            }
#pragma unroll
            for (int nt = 0; nt < 4; nt++) {
                const float* bb = Wts + (wn + nt * 8 + rg) * WSTR + kk * 8 + rt;
                uint32_t b0 = __float_as_uint(bb[0]);
                uint32_t b1 = __float_as_uint(bb[4]);
                mma8(acc[0][nt], A[0], b0, b1);
                mma8(acc[1][nt], A[1], b0, b1);
            }
        }
        __syncthreads();
    }

#pragma unroll
    for (int mt = 0; mt < 2; mt++) {
#pragma unroll
        for (int half = 0; half < 2; half++) {
            const int row = bm + wm + mt * 16 + half * 8 + rg;
#pragma unroll
            for (int nt = 0; nt < 4; nt++) {
                const int col = bn + wn + nt * 8 + rt * 2;
                float2 o;
                o.x = acc[mt][nt][half * 2]     + bias[col];
                o.y = acc[mt][nt][half * 2 + 1] + bias[col + 1];
                if (round_out) {
                    o.x = __uint_as_float(f2tf(o.x));
                    o.y = __uint_as_float(f2tf(o.y));
                }
                *(float2*)(Y + (size_t)row * DD + col) = o;
            }
        }
    }
}

// ---------------- tf32 mma flash attention ----------------
// Block: 128 q-rows, 4 warps x 2 m16 tiles. KV tile 64, double-buffered via cp.async.
// K/V in g_K/g_V are pre-rounded to tf32 (projection epilogue) -> consumed raw.
#define FTQ 128
#define FTK 64
#define QSTR 68
#define KSTR 68
#define VSTR 72
#define NTILES (MM / FTK)

#define FLASH_SMEM_FLOATS (FTQ * QSTR + 2 * FTK * KSTR + 2 * FTK * VSTR)
#define FLASH_SMEM_BYTES  (FLASH_SMEM_FLOATS * 4)

__global__ __launch_bounds__(128, 2) void flash_mma_kernel(float* __restrict__ out)
{
    extern __shared__ float sm[];
    float* Qs  = sm;                         // [FTQ][QSTR] (staging only)
    float* KsB = Qs + FTQ * QSTR;            // [2][FTK][KSTR]
    float* VsB = KsB + 2 * FTK * KSTR;       // [2][FTK][VSTR]

    const int tid  = threadIdx.x;
    const int lane = tid & 31;
    const int warp = tid >> 5;
    const int n0 = blockIdx.x * FTQ;
    const int h  = blockIdx.y;
    const int b  = blockIdx.z;

    const float* Qg = g_Q + ((size_t)b * NN + n0) * DD + h * PP;
    const float* Kg = g_K + (size_t)b * MM * DD + h * PP;
    const float* Vg = g_V + (size_t)b * MM * DD + h * PP;

    // per-thread fill addressing: row fr, column-half fcs
    const int fr  = tid >> 1;
    const int fcs = (tid & 1) * 32;
    const float* kfill = Kg + (size_t)fr * DD + fcs;
    const float* vfill = Vg + (size_t)fr * DD + fcs;
    const uint32_t kdst[2] = { s2u(KsB + fr * KSTR + fcs),
                               s2u(KsB + FTK * KSTR + fr * KSTR + fcs) };
    const uint32_t vdst[2] = { s2u(VsB + fr * VSTR + fcs),
                               s2u(VsB + FTK * VSTR + fr * VSTR + fcs) };

    // prologue: async-fill tile 0 into buffer 0
    {
        const float* ks = kfill;
        const float* vs = vfill;
#pragma unroll
        for (int c = 0; c < 8; c++) {
            cp_async16(kdst[0] + c * 16, ks + c * 4);
            cp_async16(vdst[0] + c * 16, vs + c * 4);
        }
        cp_commit();
    }

    // fold 1/sqrt(P) and log2(e) into Q so softmax is pure ex2
    const float qscale = 0.125f * 1.4426950408889634f;

    // Q staging: one row per thread, coalesced, scale + tf32-round
    {
        const float* src = Qg + (size_t)tid * DD;
        float* dst = Qs + tid * QSTR;
#pragma unroll
        for (int c = 0; c < 16; c++) {
            float4 v = *(const float4*)(src + c * 4);
            float4 o;
            o.x = __uint_as_float(f2tf(v.x * qscale));
            o.y = __uint_as_float(f2tf(v.y * qscale));
            o.z = __uint_as_float(f2tf(v.z * qscale));
            o.w = __uint_as_float(f2tf(v.w * qscale));
            *(float4*)(dst + c * 4) = o;
        }
    }

    const int rg = lane >> 2;
    const int rt = lane & 3;
    const int wm = warp * 32;

    __syncthreads();

    // hoist Q A-fragments into registers (loop-invariant across KV tiles)
    uint32_t QA[2][8][4];
#pragma unroll
    for (int mt = 0; mt < 2; mt++) {
#pragma unroll
        for (int kk = 0; kk < 8; kk++) {
            const float* qb = Qs + (wm + mt * 16 + rg) * QSTR + kk * 8 + rt;
            QA[mt][kk][0] = __float_as_uint(qb[0]);
            QA[mt][kk][1] = __float_as_uint(qb[8 * QSTR]);
            QA[mt][kk][2] = __float_as_uint(qb[4]);
            QA[mt][kk][3] = __float_as_uint(qb[8 * QSTR + 4]);
        }
    }

    float O[2][8][4];
#pragma unroll
    for (int mt = 0; mt < 2; mt++)
#pragma unroll
        for (int nt = 0; nt < 8; nt++)
#pragma unroll
            for (int i = 0; i < 4; i++) O[mt][nt][i] = 0.f;

    float mrow[4] = {-1e30f, -1e30f, -1e30f, -1e30f};
    float lrow[4] = {0.f, 0.f, 0.f, 0.f};

    const int psrc  = (lane & ~3) | (rt >> 1);
    const int psrc2 = psrc + 2;
    const bool odd  = (lane & 1);

    for (int it = 0; it < NTILES; it++) {
        // tile it's data arrived; barrier also protects buffer (it+1)&1 from
        // being overwritten below while any warp still reads it (prev-prev tile).
        cp_wait0();
        __syncthreads();

        // prefetch next tile into the other buffer
        if (it + 1 < NTILES) {
            const int nb = (it + 1) & 1;
            const float* ks = kfill + (size_t)(it + 1) * FTK * DD;
            const float* vs = vfill + (size_t)(it + 1) * FTK * DD;
#pragma unroll
            for (int c = 0; c < 8; c++) {
                cp_async16(kdst[nb] + c * 16, ks + c * 4);
                cp_async16(vdst[nb] + c * 16, vs + c * 4);
            }
            cp_commit();
        }

        const float* Ks = KsB + (it & 1) * (FTK * KSTR);
        const float* Vs = VsB + (it & 1) * (FTK * VSTR);

        // ---- S = Q K^T (exp2 domain); A-frags in registers, K raw tf32 ----
        float S[2][8][4];
#pragma unroll
        for (int mt = 0; mt < 2; mt++)
#pragma unroll
            for (int nt = 0; nt < 8; nt++)
#pragma unroll
                for (int i = 0; i < 4; i++) S[mt][nt][i] = 0.f;

#pragma unroll
        for (int kk = 0; kk < 8; kk++) {
#pragma unroll
            for (int nt = 0; nt < 8; nt++) {
                const float* kb = Ks + (nt * 8 + rg) * KSTR + kk * 8 + rt;
                uint32_t b0 = __float_as_uint(kb[0]);
                uint32_t b1 = __float_as_uint(kb[4]);
                mma8(S[0][nt], QA[0][kk], b0, b1);
                mma8(S[1][nt], QA[1][kk], b0, b1);
            }
        }

        // ---- online softmax (base-2) ----
#pragma unroll
        for (int mt = 0; mt < 2; mt++) {
#pragma unroll
            for (int half = 0; half < 2; half++) {
                const int gi = mt * 2 + half;
                float mx = -1e30f;
#pragma unroll
                for (int nt = 0; nt < 8; nt++)
                    mx = fmaxf(mx, fmaxf(S[mt][nt][half * 2], S[mt][nt][half * 2 + 1]));
                mx = fmaxf(mx, __shfl_xor_sync(0xffffffffu, mx, 1));
                mx = fmaxf(mx, __shfl_xor_sync(0xffffffffu, mx, 2));
                const float mnew = fmaxf(mrow[gi], mx);
                const float corr = ex2(mrow[gi] - mnew);
                mrow[gi] = mnew;
                lrow[gi] *= corr;
                float lsum = 0.f;
#pragma unroll
                for (int nt = 0; nt < 8; nt++) {
                    O[mt][nt][half * 2]     *= corr;
                    O[mt][nt][half * 2 + 1] *= corr;
                    float p0 = ex2(S[mt][nt][half * 2]     - mnew);
                    float p1 = ex2(S[mt][nt][half * 2 + 1] - mnew);
                    lsum += p0 + p1;
                    S[mt][nt][half * 2]     = __uint_as_float(f2tf(p0));
                    S[mt][nt][half * 2 + 1] = __uint_as_float(f2tf(p1));
                }
                lrow[gi] += lsum;
            }
        }

        // ---- O += P V ----
#pragma unroll
        for (int kk2 = 0; kk2 < 8; kk2++) {
            uint32_t A[2][4];
#pragma unroll
            for (int mt = 0; mt < 2; mt++) {
                uint32_t p0 = __float_as_uint(S[mt][kk2][0]);
                uint32_t p1 = __float_as_uint(S[mt][kk2][1]);
                uint32_t p2 = __float_as_uint(S[mt][kk2][2]);
                uint32_t p3 = __float_as_uint(S[mt][kk2][3]);
                uint32_t u0 = __shfl_sync(0xffffffffu, p0, psrc);
                uint32_t u1 = __shfl_sync(0xffffffffu, p1, psrc);
                A[mt][0] = odd ? u1 : u0;
                uint32_t u2 = __shfl_sync(0xffffffffu, p2, psrc);
                uint32_t u3 = __shfl_sync(0xffffffffu, p3, psrc);
                A[mt][1] = odd ? u3 : u2;
                uint32_t v0 = __shfl_sync(0xffffffffu, p0, psrc2);
                uint32_t v1 = __shfl_sync(0xffffffffu, p1, psrc2);
                A[mt][2] = odd ? v1 : v0;
                uint32_t v2 = __shfl_sync(0xffffffffu, p2, psrc2);
                uint32_t v3 = __shfl_sync(0xffffffffu, p3, psrc2);
                A[mt][3] = odd ? v3 : v2;
            }
#pragma unroll
            for (int nt = 0; nt < 8; nt++) {
                const float* vb = Vs + (kk2 * 8 + rt) * VSTR + nt * 8 + rg;
                uint32_t b0 = __float_as_uint(vb[0]);
                uint32_t b1 = __float_as_uint(vb[4 * VSTR]);
                mma8(O[0][nt], A[0], b0, b1);
                mma8(O[1][nt], A[1], b0, b1);
            }
        }
        // no trailing barrier: next iteration's wait+barrier protects buffers
    }

    // ---- epilogue ----
#pragma unroll
    for (int gi = 0; gi < 4; gi++) {
        float l = lrow[gi];
        l += __shfl_xor_sync(0xffffffffu, l, 1);
        l += __shfl_xor_sync(0xffffffffu, l, 2);
        lrow[gi] = 1.f / l;
    }
#pragma unroll
    for (int mt = 0; mt < 2; mt++) {
#pragma unroll
        for (int half = 0; half < 2; half++) {
            const int row = n0 + wm + mt * 16 + half * 8 + rg;
            const float inv = lrow[mt * 2 + half];
            float* ob = out + ((size_t)b * NN + row) * DD + h * PP;
#pragma unroll
            for (int nt = 0; nt < 8; nt++) {
                float2 o;
                o.x = O[mt][nt][half * 2]     * inv;
                o.y = O[mt][nt][half * 2 + 1] * inv;
                *(float2*)(ob + nt * 8 + 2 * rt) = o;
            }
        }
    }
}

// ---------------- launch ----------------
extern "C" void kernel_launch(void* const* d_in, const int* in_sizes, int n_in,
                              void* d_out, int out_size)
{
    const float* queries = (const float*)d_in[0];
    const float* keys    = (const float*)d_in[1];
    const float* values  = (const float*)d_in[2];
    const float* Wq      = (const float*)d_in[3];
    const float* bq      = (const float*)d_in[4];
    const float* Wk      = (const float*)d_in[5];
    const float* bk      = (const float*)d_in[6];
    const float* Wv      = (const float*)d_in[7];
    const float* bv      = (const float*)d_in[8];
    float* out = (float*)d_out;

    float *pQ, *pK, *pV;
    cudaGetSymbolAddress((void**)&pQ, g_Q);
    cudaGetSymbolAddress((void**)&pK, g_K);
    cudaGetSymbolAddress((void**)&pV, g_V);

    // projections: Q full-precision output; K/V tf32-rounded outputs
    dim3 pgrid(DD / PBN, (BB * NN) / PBM);
    gemm_tf32_kernel<<<pgrid, 256>>>(queries, Wq, bq, pQ, 0);
    gemm_tf32_kernel<<<pgrid, 256>>>(keys,    Wk, bk, pK, 1);
    gemm_tf32_kernel<<<pgrid, 256>>>(values,  Wv, bv, pV, 1);

    cudaFuncSetAttribute(flash_mma_kernel, cudaFuncAttributeMaxDynamicSharedMemorySize,
                         FLASH_SMEM_BYTES);
    dim3 fgrid(NN / FTQ, HH, BB);
    flash_mma_kernel<<<fgrid, 128, FLASH_SMEM_BYTES>>>(out);
}